// round 1
// baseline (speedup 1.0000x reference)
#include <cuda_runtime.h>

// ---------------- problem constants ----------------
#define B_    8
#define HDIM  112
#define WDIM  112
#define CDIM  384
#define NHEAD 12
#define HD    32
#define WS    7
#define SSH   3
#define NTOK  49          // WS*WS
#define NWH   16          // HDIM/WS
#define NWW   16
#define NWIN  256         // NWH*NWW
#define BW    (B_ * NWIN)         // 2048 windows total
#define MROWS (BW * NTOK)         // 100352
#define QKVN  (3 * CDIM)          // 1152

// GEMM tiling
#define BM 128
#define BN 64
#define BK 16

// ---------------- scratch (static device globals; no allocation) ----------------
__device__ float gQ[(size_t)BW * NHEAD * NTOK * HD];   // 154 MB
__device__ float gK[(size_t)BW * NHEAD * NTOK * HD];   // 154 MB
__device__ float gV[(size_t)BW * NHEAD * NTOK * HD];   // 154 MB
__device__ float gAttnOut[(size_t)MROWS * CDIM];       // 154 MB
__device__ float gBias[NHEAD * NTOK * NTOK];           // 115 KB

// ---------------- shift/window <-> original row mapping (bijection, no padding) -
__device__ __forceinline__ int src_row(int m) {
    int w  = m / NTOK;
    int n  = m - w * NTOK;
    int b  = w / NWIN;
    int wi = w - b * NWIN;
    int wy = wi / NWW;
    int wx = wi - wy * NWW;
    int ty = n / WS;
    int tx = n - ty * WS;
    int sy = wy * WS + ty;
    int sx = wx * WS + tx;
    int oy = sy + SSH; if (oy >= HDIM) oy -= HDIM;   // shifted[s] = orig[(s+SS)%H]
    int ox = sx + SSH; if (ox >= WDIM) ox -= WDIM;
    return (b * HDIM + oy) * WDIM + ox;              // row in (B*H*W)
}

// ---------------- relative position bias table expansion ----------------
__global__ void bias_kernel(const float* __restrict__ rel_pos_table) {
    int idx = blockIdx.x * blockDim.x + threadIdx.x;
    if (idx >= NHEAD * NTOK * NTOK) return;
    int h = idx / (NTOK * NTOK);
    int r = idx - h * (NTOK * NTOK);
    int i = r / NTOK;
    int j = r - i * NTOK;
    // c(n) = (2*WS-1)*(n/WS) + n%WS ; ridx[i][j] = c(i) + c(WS*WS-1-j)
    int ci = 13 * (i / 7) + (i % 7);
    int jr = 48 - j;
    int cj = 13 * (jr / 7) + (jr % 7);
    gBias[idx] = rel_pos_table[(ci + cj) * NHEAD + h];
}

// ---------------- K1: QKV GEMM fused with shifted-window gather ----------------
// C[m, col] = sum_k x[src_row(m), k] * qkv_w[k, col] + qkv_b[col]
// scatter: col -> (t, h, d); write Q/K/V[w][h][n][d]
__global__ __launch_bounds__(256) void qkv_gemm(const float* __restrict__ x,
                                                const float* __restrict__ qkv_w,
                                                const float* __restrict__ qkv_b) {
    __shared__ float As[BK][BM];
    __shared__ float Bs[BK][BN];
    __shared__ int   rowIdx[BM];

    int tid = threadIdx.x;
    int m0  = blockIdx.x * BM;
    int bn  = blockIdx.y;

    if (tid < BM) rowIdx[tid] = src_row(m0 + tid);
    __syncthreads();

    float acc[8][4] = {};
    int ty = tid >> 4;        // 0..15 -> 8 rows each
    int tx = tid & 15;        // 0..15 -> 4 cols each
    int qd = tid & 3;         // A-load: quad within row
    int r0 = tid >> 2;        // A-load: row 0..63 (+64)
    int br = tid >> 4;        // B-load: k row 0..15
    int bc = (tid & 15) * 4;  // B-load: col

    for (int kt = 0; kt < CDIM / BK; ++kt) {
        int k0 = kt * BK;
#pragma unroll
        for (int s = 0; s < 2; ++s) {
            int r = r0 + s * 64;
            float4 a = *(const float4*)(x + (size_t)rowIdx[r] * CDIM + k0 + qd * 4);
            As[qd * 4 + 0][r] = a.x;
            As[qd * 4 + 1][r] = a.y;
            As[qd * 4 + 2][r] = a.z;
            As[qd * 4 + 3][r] = a.w;
        }
        *(float4*)&Bs[br][bc] =
            *(const float4*)(qkv_w + (size_t)(k0 + br) * QKVN + bn * BN + bc);
        __syncthreads();
#pragma unroll
        for (int k = 0; k < BK; ++k) {
            float4 a0 = *(float4*)&As[k][ty * 8];
            float4 a1 = *(float4*)&As[k][ty * 8 + 4];
            float4 b  = *(float4*)&Bs[k][tx * 4];
            float av[8] = {a0.x, a0.y, a0.z, a0.w, a1.x, a1.y, a1.z, a1.w};
            float bv[4] = {b.x, b.y, b.z, b.w};
#pragma unroll
            for (int i = 0; i < 8; ++i)
#pragma unroll
                for (int j = 0; j < 4; ++j) acc[i][j] += av[i] * bv[j];
        }
        __syncthreads();
    }

    int col = bn * BN + tx * 4;          // multiple of 4; 64-wide block within one t
    int t   = col / CDIM;                // 0=Q 1=K 2=V
    int cc  = col - t * CDIM;
    int h   = cc / HD;                   // 4-col group never straddles a head
    int d   = cc - h * HD;
    float* dstT = (t == 0) ? gQ : (t == 1) ? gK : gV;
    float4 bb = *(const float4*)(qkv_b + col);
#pragma unroll
    for (int i = 0; i < 8; ++i) {
        int m = m0 + ty * 8 + i;
        int w = m / NTOK;
        int n = m - w * NTOK;
        float4 v = make_float4(acc[i][0] + bb.x, acc[i][1] + bb.y,
                               acc[i][2] + bb.z, acc[i][3] + bb.w);
        *(float4*)(dstT + ((size_t)(w * NHEAD + h) * NTOK + n) * HD + d) = v;
    }
}

// ---------------- K2: per-(window,head) attention ----------------
__global__ __launch_bounds__(64) void attn_kernel() {
    const float scale = 0.17677669529663689f;  // 32^-0.5
    int bid = blockIdx.x;
    int w   = bid / NHEAD;
    int h   = bid - w * NHEAD;

    __shared__ float Qs[NTOK][HD];
    __shared__ float Ks[NTOK][HD];
    __shared__ float Vs[NTOK][HD];
    __shared__ float Ps[NTOK][NTOK];   // softmax probabilities (stride 49: odd -> conflict-free)
    __shared__ int   rcnt[NTOK];

    int tid = threadIdx.x;
    size_t base = (size_t)(w * NHEAD + h) * NTOK * HD;

    for (int idx = tid; idx < NTOK * HD; idx += 64) {
        ((float*)Qs)[idx] = gQ[base + idx] * scale;
        ((float*)Ks)[idx] = gK[base + idx];
        ((float*)Vs)[idx] = gV[base + idx];
    }
    if (tid < NTOK) {
        int wi = w % NWIN;
        int wy = wi / NWW, wx = wi - wy * NWW;
        int ty = tid / WS, tx = tid - ty * WS;
        int sy = wy * WS + ty, sx = wx * WS + tx;
        int idh = (sy < HDIM - WS) ? 0 : (sy < HDIM - SSH) ? 1 : 2;
        int idw = (sx < WDIM - WS) ? 0 : (sx < WDIM - SSH) ? 1 : 2;
        rcnt[tid] = idh * 3 + idw;
    }
    __syncthreads();

    if (tid < NTOK) {
        float q[HD];
#pragma unroll
        for (int d = 0; d < HD; ++d) q[d] = Qs[tid][d];

        const float* biasRow = gBias + (h * NTOK + tid) * NTOK;
        int myc = rcnt[tid];
        float mx = -1e30f;
        for (int j = 0; j < NTOK; ++j) {
            float s = 0.f;
#pragma unroll
            for (int d = 0; d < HD; d += 4) {
                float4 kv = *(float4*)&Ks[j][d];
                s += q[d] * kv.x + q[d + 1] * kv.y + q[d + 2] * kv.z + q[d + 3] * kv.w;
            }
            s += biasRow[j];
            if (rcnt[j] != myc) s -= 100.0f;
            Ps[tid][j] = s;
            mx = fmaxf(mx, s);
        }
        float sum = 0.f;
        for (int j = 0; j < NTOK; ++j) {
            float e = __expf(Ps[tid][j] - mx);
            Ps[tid][j] = e;
            sum += e;
        }
        float inv = 1.0f / sum;

        float o[HD] = {};
        for (int j = 0; j < NTOK; ++j) {
            float pj = Ps[tid][j] * inv;
#pragma unroll
            for (int d = 0; d < HD; d += 4) {
                float4 vv = *(float4*)&Vs[j][d];
                o[d]     += pj * vv.x;
                o[d + 1] += pj * vv.y;
                o[d + 2] += pj * vv.z;
                o[d + 3] += pj * vv.w;
            }
        }
        float* dst = gAttnOut + (size_t)(w * NTOK + tid) * CDIM + h * HD;
#pragma unroll
        for (int d = 0; d < HD; d += 4)
            *(float4*)(dst + d) = make_float4(o[d], o[d + 1], o[d + 2], o[d + 3]);
    }
}

// ---------------- K3: proj GEMM fused with window-reverse + roll scatter --------
__global__ __launch_bounds__(256) void proj_gemm(const float* __restrict__ pw,
                                                 const float* __restrict__ pb,
                                                 float* __restrict__ out) {
    __shared__ float As[BK][BM];
    __shared__ float Bs[BK][BN];

    int tid = threadIdx.x;
    int m0  = blockIdx.x * BM;
    int bn  = blockIdx.y;

    float acc[8][4] = {};
    int ty = tid >> 4;
    int tx = tid & 15;
    int qd = tid & 3;
    int r0 = tid >> 2;
    int br = tid >> 4;
    int bc = (tid & 15) * 4;

    for (int kt = 0; kt < CDIM / BK; ++kt) {
        int k0 = kt * BK;
#pragma unroll
        for (int s = 0; s < 2; ++s) {
            int r = r0 + s * 64;
            float4 a = *(const float4*)(gAttnOut + (size_t)(m0 + r) * CDIM + k0 + qd * 4);
            As[qd * 4 + 0][r] = a.x;
            As[qd * 4 + 1][r] = a.y;
            As[qd * 4 + 2][r] = a.z;
            As[qd * 4 + 3][r] = a.w;
        }
        *(float4*)&Bs[br][bc] =
            *(const float4*)(pw + (size_t)(k0 + br) * CDIM + bn * BN + bc);
        __syncthreads();
#pragma unroll
        for (int k = 0; k < BK; ++k) {
            float4 a0 = *(float4*)&As[k][ty * 8];
            float4 a1 = *(float4*)&As[k][ty * 8 + 4];
            float4 b  = *(float4*)&Bs[k][tx * 4];
            float av[8] = {a0.x, a0.y, a0.z, a0.w, a1.x, a1.y, a1.z, a1.w};
            float bv[4] = {b.x, b.y, b.z, b.w};
#pragma unroll
            for (int i = 0; i < 8; ++i)
#pragma unroll
                for (int j = 0; j < 4; ++j) acc[i][j] += av[i] * bv[j];
        }
        __syncthreads();
    }

    int col = bn * BN + tx * 4;
    float4 bb = *(const float4*)(pb + col);
#pragma unroll
    for (int i = 0; i < 8; ++i) {
        int m = m0 + ty * 8 + i;
        int orow = src_row(m);   // inverse shift == forward mapping (bijection)
        float4 v = make_float4(acc[i][0] + bb.x, acc[i][1] + bb.y,
                               acc[i][2] + bb.z, acc[i][3] + bb.w);
        *(float4*)(out + (size_t)orow * CDIM + col) = v;
    }
}

// ---------------- launch ----------------
extern "C" void kernel_launch(void* const* d_in, const int* in_sizes, int n_in,
                              void* d_out, int out_size) {
    (void)in_sizes; (void)n_in; (void)out_size;
    const float* x      = (const float*)d_in[0];
    const float* qkv_w  = (const float*)d_in[1];
    const float* qkv_b  = (const float*)d_in[2];
    const float* proj_w = (const float*)d_in[3];
    const float* proj_b = (const float*)d_in[4];
    const float* rpt    = (const float*)d_in[5];
    float* out = (float*)d_out;

    bias_kernel<<<(NHEAD * NTOK * NTOK + 255) / 256, 256>>>(rpt);

    dim3 g1(MROWS / BM, QKVN / BN);   // (784, 18)
    qkv_gemm<<<g1, 256>>>(x, qkv_w, qkv_b);

    attn_kernel<<<BW * NHEAD, 64>>>();  // 24576 blocks

    dim3 g3(MROWS / BM, CDIM / BN);   // (784, 6)
    proj_gemm<<<g3, 256>>>(proj_w, proj_b, out);
}